// round 17
// baseline (speedup 1.0000x reference)
#include <cuda_runtime.h>
#include <cuda_fp16.h>
#include <cstdint>

typedef unsigned long long u64;
typedef uint32_t u32;

#define NB 4096
#define NE 16
#define ND 512
#define NH 2048

#define KC 64                          // k-chunk: 64 fp16 = 128B rows
#define TILE 16384                     // 128 x 64 fp16 tile bytes
#define STAGE (2 * TILE)               // x tile + w tile per chunk
#define NSTAGE 6
#define SMEM_TOTAL (NSTAGE * STAGE)    // 196608 B
#define NSM 148
#define NTILES 1024                    // 16 hx * 32 my * 2 z

// ---------------- scratch (device globals; no allocations allowed) ----------
__device__ __half g_xh[NB * ND];
__device__ __half g_wh[NE * NH * ND];
__device__ float  g_dcomb[NE * NH];

// ---------------- PTX helpers ----------------------------------------------
__device__ __forceinline__ u32 smem_u32(const void* p) {
    u32 a;
    asm("{ .reg .u64 t; cvta.to.shared.u64 t, %1; cvt.u32.u64 %0, t; }" : "=r"(a) : "l"(p));
    return a;
}
__device__ __forceinline__ void cp16(u32 dst, const void* src) {
    asm volatile("cp.async.cg.shared.global [%0], [%1], 16;" :: "r"(dst), "l"(src) : "memory");
}
__device__ __forceinline__ void cp_commit() { asm volatile("cp.async.commit_group;" ::: "memory"); }
__device__ __forceinline__ void cp_wait1()  { asm volatile("cp.async.wait_group 1;" ::: "memory"); }

__device__ __forceinline__ void ldsm4(u32& r0, u32& r1, u32& r2, u32& r3, u32 addr) {
    asm volatile("ldmatrix.sync.aligned.m8n8.x4.shared.b16 {%0,%1,%2,%3}, [%4];"
                 : "=r"(r0), "=r"(r1), "=r"(r2), "=r"(r3) : "r"(addr));
}
__device__ __forceinline__ void mma16816(float* c, const u32* a, const u32* b) {
    asm volatile("mma.sync.aligned.m16n8k16.row.col.f32.f16.f16.f32 "
                 "{%0,%1,%2,%3}, {%4,%5,%6,%7}, {%8,%9}, {%0,%1,%2,%3};"
                 : "+f"(c[0]), "+f"(c[1]), "+f"(c[2]), "+f"(c[3])
                 : "r"(a[0]), "r"(a[1]), "r"(a[2]), "r"(a[3]), "r"(b[0]), "r"(b[1]));
}

__device__ __forceinline__ u32 swz128(u32 off) { return off ^ ((off >> 3) & 0x70); }

__device__ __forceinline__ u32 h2u(__half2 h) { return *(u32*)&h; }

// ---------------- fused prep + zero kernel -----------------------------------
// blocks [0, 4096):      W rows -> fp16 (16B stores) + d = bias - c_e.W_row
// blocks [4096, 5120):   x -> fp16 (16B stores)
// blocks [5120, 13312):  zero out
__global__ void prep_kernel(const float* __restrict__ x,
                            const float* __restrict__ W,
                            const float* __restrict__ centers,
                            const float* __restrict__ bias,
                            float4* __restrict__ out) {
    int b = blockIdx.x;
    if (b < 4096) {
        int gw   = b * 8 + (threadIdx.x >> 5);
        int lane = threadIdx.x & 31;
        int e = gw >> 11;
        const float4* wr = (const float4*)(W + (size_t)gw * ND);
        const float4* cr = (const float4*)(centers + (size_t)e * ND);
        uint4* ph = (uint4*)(g_wh + (size_t)gw * ND);
        float s = 0.f;
#pragma unroll
        for (int i = 0; i < 2; i++) {
            int q = lane + 32 * i;          // uint4 (8-half) index, 0..63
            float4 wa = wr[2 * q], wb = wr[2 * q + 1];
            float4 ca = cr[2 * q], cb = cr[2 * q + 1];
            s += wa.x * ca.x + wa.y * ca.y + wa.z * ca.z + wa.w * ca.w
               + wb.x * cb.x + wb.y * cb.y + wb.z * cb.z + wb.w * cb.w;
            uint4 h;
            h.x = h2u(__floats2half2_rn(wa.x, wa.y));
            h.y = h2u(__floats2half2_rn(wa.z, wa.w));
            h.z = h2u(__floats2half2_rn(wb.x, wb.y));
            h.w = h2u(__floats2half2_rn(wb.z, wb.w));
            ph[q] = h;
        }
#pragma unroll
        for (int o = 16; o; o >>= 1) s += __shfl_xor_sync(0xffffffffu, s, o);
        if (lane == 0) g_dcomb[gw] = bias[gw] - s;
    } else if (b < 5120) {
        int i = (b - 4096) * 256 + threadIdx.x;   // 8-float group index
        const float4* xr = (const float4*)x;
        float4 a = xr[2 * i], c = xr[2 * i + 1];
        uint4 h;
        h.x = h2u(__floats2half2_rn(a.x, a.y));
        h.y = h2u(__floats2half2_rn(a.z, a.w));
        h.z = h2u(__floats2half2_rn(c.x, c.y));
        h.w = h2u(__floats2half2_rn(c.z, c.w));
        ((uint4*)g_xh)[i] = h;
    } else {
        out[(size_t)(b - 5120) * 256 + threadIdx.x] = make_float4(0.f, 0.f, 0.f, 0.f);
    }
}

// ---------------- main GEMM kernel (persistent) -------------------------------
// grid 148; 256 threads, 8 warps (2m x 4n of 64x32). CTA p processes tiles
// p, p+148, ... of the 1024-tile list. 6-stage cp.async ring runs continuously
// across tile boundaries. SMSP warp pairs (wid, wid+4) are DE-PHASED: warps
// with wid>=4 process each pair's chunks in order (c1, c0), so one warp's
// LDSM windows overlap the other's MMA blocks on the shared tensor pipe.

__device__ __forceinline__ void tparams(int t, int& mb, int& hb, int& eb) {
    hb = (t & 15) << 7;                // hx * 128
    mb = ((t >> 4) & 31) << 7;         // my * 128
    eb = (t >> 9) << 3;                // z * 8
}

// load chunk k (0/1) of local pair lp; stage ring indexed by global chunk
__device__ __forceinline__ void load_chunk_g(int lp, int k, int first_tile,
                                             u32 sb, int tid) {
    int t = first_tile + NSM * (lp >> 5);
    int mb, hb, eb;
    tparams(t, mb, hb, eb);
    int c = ((lp & 31) << 1) | k;      // chunk within tile, 0..63
    int e = eb + (c >> 3), kc = (c & 7) * KC;
    u32 dst = sb + (u32)((2 * lp + k) % NSTAGE) * STAGE;
    int row = tid >> 3, cc = tid & 7;
    u32 so = swz128((u32)(row * 128 + cc * 16));
    const __half* pxh = g_xh + (size_t)(mb + row) * ND + kc + cc * 8;
    const __half* pwh = g_wh + (size_t)(e * NH + hb + row) * ND + kc + cc * 8;
#pragma unroll
    for (int i = 0; i < 4; i++) {
        u32 d = dst + so + (u32)i * 4096;          // +32 rows per step
        size_t eo = (size_t)(32 * i) * ND;
        cp16(d + 0 * TILE, pxh + eo);
        cp16(d + 1 * TILE, pwh + eo);
    }
}

__device__ __forceinline__ void load_frags(int ks, u32 Ah, u32 Bh, int wm, int wn,
                                           int lane, u32 ah[4][4], u32 bh[4][2]) {
    u32 arel = swz128((u32)((lane & 15) * 128 + ks * 32 + (lane >> 4) * 16));
#pragma unroll
    for (int mt = 0; mt < 4; mt++) {
        u32 ao = (u32)((wm + mt * 16) * 128) + arel;
        ldsm4(ah[mt][0], ah[mt][1], ah[mt][2], ah[mt][3], Ah + ao);
    }
    u32 brel = swz128((u32)((lane & 7) * 128 + ks * 32 + ((lane >> 3) & 1) * 16));
#pragma unroll
    for (int pr = 0; pr < 2; pr++) {
        u32 bo = (u32)((wn + pr * 16 + ((lane >> 4) & 1) * 8) * 128) + brel;
        ldsm4(bh[pr * 2][0], bh[pr * 2][1], bh[pr * 2 + 1][0], bh[pr * 2 + 1][1], Bh + bo);
    }
}

#define MMA_BLOCK(buf)                                                       \
    _Pragma("unroll")                                                        \
    for (int mt = 0; mt < 4; mt++)                                           \
        _Pragma("unroll")                                                    \
        for (int nt = 0; nt < 4; nt++)                                       \
            mma16816(acc[mt][nt], ah[buf][mt], bh[buf][nt]);

__global__ void __launch_bounds__(256, 1)
gemm_kernel(float* __restrict__ out) {
    extern __shared__ char smem[];
    u32 sb = smem_u32(smem);
    const int tid = threadIdx.x, wid = tid >> 5, lane = tid & 31;
    const int wm = (wid >> 2) * 64, wn = (wid & 3) * 32;
    const int ord = (wid >> 2) & 1;    // 0: process (c0,c1); 1: process (c1,c0)
    const int first_tile = blockIdx.x;

    const int ntiles = (NTILES - first_tile + NSM - 1) / NSM;   // 6 or 7
    const int total_pairs = ntiles * 32;

    // prologue: pairs 0 and 1 (chunks 0..3), one commit per pair
    load_chunk_g(0, 0, first_tile, sb, tid);
    load_chunk_g(0, 1, first_tile, sb, tid); cp_commit();
    load_chunk_g(1, 0, first_tile, sb, tid);
    load_chunk_g(1, 1, first_tile, sb, tid); cp_commit();

    float acc[4][4][4], oacc[4][4][4];
#pragma unroll
    for (int a = 0; a < 4; a++)
#pragma unroll
        for (int b = 0; b < 4; b++)
#pragma unroll
            for (int c = 0; c < 4; c++) { acc[a][b][c] = 0.f; oacc[a][b][c] = 0.f; }

    u32 ah[2][4][4], bh[2][4][2];
    float2 dreg[4];

    for (int lp = 0; lp < total_pairs; lp++) {
        int mb, hb, eb;
        tparams(first_tile + NSM * (lp >> 5), mb, hb, eb);

        cp_wait1();                    // groups up to G_lp complete
        __syncthreads();

        u32 s0 = sb + (u32)((2 * lp)     % NSTAGE) * STAGE;
        u32 s1 = sb + (u32)((2 * lp + 1) % NSTAGE) * STAGE;
        // de-phase: warp's FIRST chunk is c0 for ord=0, c1 for ord=1
        u32 Xa = ord ? s1 : s0, Ya = ord ? s0 : s1;
        u32 Xb = Xa + TILE, Yb = Ya + TILE;

        // ---- first chunk, ks0: frags + MMAs FIRST (LDGSTS burst deferred) ----
        load_frags(0, Xa, Xb, wm, wn, lane, ah[0], bh[0]);
        load_frags(1, Xa, Xb, wm, wn, lane, ah[1], bh[1]);
        MMA_BLOCK(0)

        // ---- global->smem prefetch for pair lp+2 rides in the MMA shadow ----
        if (lp + 2 < total_pairs) {
            load_chunk_g(lp + 2, 0, first_tile, sb, tid);
            load_chunk_g(lp + 2, 1, first_tile, sb, tid);
        }
        cp_commit();

        // prefetch the epilogue bias one pair early (L2 hit, off critical path)
        if ((lp & 3) == 2) {
            const float2* dp = (const float2*)
                (g_dcomb + (size_t)(eb + ((lp & 31) >> 2)) * NH + hb + wn);
#pragma unroll
            for (int nt = 0; nt < 4; nt++) dreg[nt] = dp[nt * 4 + (lane & 3)];
        }

        // ---- first chunk, ks1..3 (at ks3 preload second chunk's ks0) ----
        load_frags(2, Xa, Xb, wm, wn, lane, ah[0], bh[0]);
        MMA_BLOCK(1)
        load_frags(3, Xa, Xb, wm, wn, lane, ah[1], bh[1]);
        MMA_BLOCK(0)
        load_frags(0, Ya, Yb, wm, wn, lane, ah[0], bh[0]);
        MMA_BLOCK(1)

        // ---- second chunk ----
#pragma unroll
        for (int ks = 0; ks < 4; ks++) {
            int cur = ks & 1;
            if (ks < 3) load_frags(ks + 1, Ya, Yb, wm, wn, lane, ah[cur ^ 1], bh[cur ^ 1]);
            MMA_BLOCK(cur)
        }

        if ((lp & 3) == 3) {           // finished local expert: relu + accumulate
#pragma unroll
            for (int nt = 0; nt < 4; nt++) {
                float2 d2 = dreg[nt];
#pragma unroll
                for (int mt = 0; mt < 4; mt++) {
                    oacc[mt][nt][0] += fmaxf(acc[mt][nt][0] + d2.x, 0.f);
                    oacc[mt][nt][1] += fmaxf(acc[mt][nt][1] + d2.y, 0.f);
                    oacc[mt][nt][2] += fmaxf(acc[mt][nt][2] + d2.x, 0.f);
                    oacc[mt][nt][3] += fmaxf(acc[mt][nt][3] + d2.y, 0.f);
                    acc[mt][nt][0] = 0.f; acc[mt][nt][1] = 0.f;
                    acc[mt][nt][2] = 0.f; acc[mt][nt][3] = 0.f;
                }
            }
        }

        if ((lp & 31) == 31) {         // tile done: accumulate into out, reset
#pragma unroll
            for (int mt = 0; mt < 4; mt++)
#pragma unroll
                for (int nt = 0; nt < 4; nt++) {
                    int r0 = mb + wm + mt * 16 + (lane >> 2);
                    int cc = hb + wn + nt * 8 + 2 * (lane & 3);
                    float* p0 = out + (size_t)r0 * NH + cc;
                    float* p1 = out + (size_t)(r0 + 8) * NH + cc;
                    atomicAdd(p0,     oacc[mt][nt][0]);
                    atomicAdd(p0 + 1, oacc[mt][nt][1]);
                    atomicAdd(p1,     oacc[mt][nt][2]);
                    atomicAdd(p1 + 1, oacc[mt][nt][3]);
                    oacc[mt][nt][0] = 0.f; oacc[mt][nt][1] = 0.f;
                    oacc[mt][nt][2] = 0.f; oacc[mt][nt][3] = 0.f;
                }
        }
    }
}

// ---------------- launch -----------------------------------------------------
extern "C" void kernel_launch(void* const* d_in, const int* in_sizes, int n_in,
                              void* d_out, int out_size) {
    const float* x       = (const float*)d_in[0];  // [B, D]
    const float* centers = (const float*)d_in[1];  // [E, D]
    const float* W       = (const float*)d_in[2];  // [E, H, D]
    const float* bias    = (const float*)d_in[3];  // [E, H]
    float* out = (float*)d_out;                    // [B, H]

    cudaFuncSetAttribute(gemm_kernel, cudaFuncAttributeMaxDynamicSharedMemorySize, SMEM_TOTAL);

    // 4096 W blocks + 1024 x blocks + 8192 zero blocks
    prep_kernel<<<4096 + 1024 + 8192, 256>>>(x, W, centers, bias, (float4*)out);

    gemm_kernel<<<NSM, 256, SMEM_TOTAL>>>(out);
}